// round 1
// baseline (speedup 1.0000x reference)
#include <cuda_runtime.h>
#include <math.h>

#define BB 512
#define SS 30
#define CC 16
#define HH 768
#define RR 4
#define NP 5                    // W_s + 4 relation weights
#define NW (NP*HH)              // 3840 packed output cols
#define NSLOT (BB*SS)           // 15360
#define NCLS  (BB*CC)           // 8192
#define NROW  (NSLOT+NCLS)      // 23552 = 184*128
#define EPSV 1e-5f

// ---------------- scratch (__device__ globals; no allocations) ----------------
__device__ float g_X0[(size_t)NROW*HH];     // state ping
__device__ float g_X1[(size_t)NROW*HH];     // state pong
__device__ float g_U [(size_t)NROW*HH];     // pre-gate updated state
__device__ float g_Y [(size_t)NROW*NW];     // packed projection outputs (~362 MB)
__device__ float g_Wcat[(size_t)HH*NW];     // packed [W_s | W_r0..3]
__device__ float g_bcat[NW];

// ---------------- init: X0 = concat(slots, cls) rows ----------------
__global__ void k_init(const float* __restrict__ slots, const float* __restrict__ cls) {
    size_t i = (size_t)blockIdx.x * blockDim.x + threadIdx.x;
    const size_t n0 = (size_t)NSLOT * HH;
    const size_t n1 = (size_t)NCLS * HH;
    if (i < n0) g_X0[i] = slots[i];
    if (i < n1) g_X0[n0 + i] = cls[i];
}

// ---------------- pack weights: Wcat[h][p*H+k] ----------------
__global__ void k_pack(const float* __restrict__ Ws, const float* __restrict__ bs,
                       const float* __restrict__ Wr, const float* __restrict__ br) {
    size_t i = (size_t)blockIdx.x * blockDim.x + threadIdx.x;
    if (i < (size_t)HH * NW) {
        int h = (int)(i / NW);
        int j = (int)(i % NW);
        int p = j / HH, k = j % HH;
        g_Wcat[i] = (p == 0) ? Ws[(size_t)h*HH + k]
                             : Wr[((size_t)(p-1)*HH + h)*HH + k];
    }
    if (i < NW) {
        int p = (int)(i / HH), k = (int)(i % HH);
        g_bcat[i] = (p == 0) ? bs[k] : br[(size_t)(p-1)*HH + k];
    }
}

// ---------------- SGEMM 1: Y = X @ Wcat + bcat ----------------
// BM=BN=128, BK=16, 256 threads, 8x8 per thread. All dims divide exactly.
__global__ void __launch_bounds__(256) k_gemm_proj(int layer) {
    const float* __restrict__ A = layer ? g_X1 : g_X0;   // [NROW, HH]
    const int bn = blockIdx.x * 128;                      // col in NW
    const int bm = blockIdx.y * 128;                      // row
    __shared__ float As[16][128];
    __shared__ float Bs[16][128];
    const int tid = threadIdx.x;
    const int tx = tid & 15, ty = tid >> 4;

    float acc[8][8];
#pragma unroll
    for (int i = 0; i < 8; i++)
#pragma unroll
        for (int j = 0; j < 8; j++) acc[i][j] = 0.f;

    for (int k0 = 0; k0 < HH; k0 += 16) {
#pragma unroll
        for (int l = 0; l < 2; l++) {
            int idx = tid + l * 256;
            int ar = idx >> 2, ak = (idx & 3) << 2;
            float4 va = *(const float4*)(A + (size_t)(bm + ar) * HH + k0 + ak);
            As[ak+0][ar] = va.x; As[ak+1][ar] = va.y;
            As[ak+2][ar] = va.z; As[ak+3][ar] = va.w;
            int brr = idx >> 5, bc = (idx & 31) << 2;
            float4 vb = *(const float4*)(g_Wcat + (size_t)(k0 + brr) * NW + bn + bc);
            *(float4*)&Bs[brr][bc] = vb;
        }
        __syncthreads();
#pragma unroll
        for (int k = 0; k < 16; k++) {
            float a[8], b[8];
#pragma unroll
            for (int j = 0; j < 8; j++) { a[j] = As[k][ty*8+j]; b[j] = Bs[k][tx*8+j]; }
#pragma unroll
            for (int i = 0; i < 8; i++)
#pragma unroll
                for (int j = 0; j < 8; j++) acc[i][j] += a[i] * b[j];
        }
        __syncthreads();
    }
#pragma unroll
    for (int i = 0; i < 8; i++) {
        size_t row = (size_t)(bm + ty*8 + i);
#pragma unroll
        for (int j = 0; j < 8; j += 4) {
            int col = bn + tx*8 + j;
            float4 v;
            v.x = acc[i][j+0] + g_bcat[col+0];
            v.y = acc[i][j+1] + g_bcat[col+1];
            v.z = acc[i][j+2] + g_bcat[col+2];
            v.w = acc[i][j+3] + g_bcat[col+3];
            *(float4*)(g_Y + row * NW + col) = v;
        }
    }
}

// ---------------- mixing: U = Y[:,blk0] + normalized attention message terms ----------------
// grid (BB, HH/128), 128 threads: thread = k within a 128-wide k-tile.
__global__ void __launch_bounds__(128) k_mix(const float* __restrict__ a_cur,
                                             const float* __restrict__ a_slot,
                                             const float* __restrict__ a_last,
                                             const float* __restrict__ a_dom) {
    const int b  = blockIdx.x;
    const int k0 = blockIdx.y * 128;
    const int t  = threadIdx.x;

    __shared__ float sCur[SS*CC], sLast[SS*CC], sSlot[SS*SS], sDom[SS*SS];
    __shared__ float invColCur[CC], invColLast[CC];
    __shared__ float invRowCur[SS], invRowSlot[SS], invRowLast[SS], invRowDom[SS];
    __shared__ float T0[SS*128];
    __shared__ float T1[SS*128];

    for (int i = t; i < SS*CC; i += 128) {
        sCur[i]  = a_cur [(size_t)b*SS*CC + i];
        sLast[i] = a_last[(size_t)b*SS*CC + i];
    }
    for (int i = t; i < SS*SS; i += 128) {
        sSlot[i] = a_slot[(size_t)b*SS*SS + i];
        sDom[i]  = a_dom [(size_t)b*SS*SS + i];
    }
    __syncthreads();
    if (t < CC) {
        float s1 = 0.f, s2 = 0.f;
        for (int s = 0; s < SS; s++) { s1 += sCur[s*CC+t]; s2 += sLast[s*CC+t]; }
        invColCur[t]  = 1.f / (s1 + EPSV);
        invColLast[t] = 1.f / (s2 + EPSV);
    } else if (t >= 32 && t < 32 + SS) {
        int s = t - 32; float s1 = 0.f, s2 = 0.f;
        for (int c = 0; c < CC; c++) { s1 += sCur[s*CC+c]; s2 += sLast[s*CC+c]; }
        invRowCur[s]  = 1.f / (s1 + EPSV);
        invRowLast[s] = 1.f / (s2 + EPSV);
    } else if (t >= 64 && t < 64 + SS) {
        int s = t - 64; float s1 = 0.f, s2 = 0.f;
        for (int j = 0; j < SS; j++) { s1 += sSlot[s*SS+j]; s2 += sDom[s*SS+j]; }
        invRowSlot[s] = 1.f / (s1 + EPSV);
        invRowDom[s]  = 1.f / (s2 + EPSV);
    }
    __syncthreads();

    // ---- Phase A: cls_u rows (uses rel_slots blocks 1 and 3) ----
    for (int s = 0; s < SS; s++) {
        size_t base = (size_t)(b*SS + s) * NW + k0 + t;
        T0[s*128 + t] = g_Y[base + 1*HH];
        T1[s*128 + t] = g_Y[base + 3*HH];
    }
    __syncthreads();
    for (int c = 0; c < CC; c++) {
        float a1 = 0.f, a3 = 0.f;
#pragma unroll
        for (int s = 0; s < SS; s++) {
            a1 += sCur[s*CC+c]  * T0[s*128+t];
            a3 += sLast[s*CC+c] * T1[s*128+t];
        }
        size_t crow = (size_t)NSLOT + (size_t)b*CC + c;
        float base = g_Y[crow * NW + k0 + t];
        g_U[crow * HH + k0 + t] = base + invColCur[c]*a1 + invColLast[c]*a3;
    }
    __syncthreads();

    // ---- Phase B1: slots_u from rel_cls blk1 + rel_slots blk2 ----
    for (int c = 0; c < CC; c++)
        T0[c*128 + t] = g_Y[((size_t)NSLOT + (size_t)b*CC + c) * NW + 1*HH + k0 + t];
    for (int s = 0; s < SS; s++)
        T1[s*128 + t] = g_Y[(size_t)(b*SS + s) * NW + 2*HH + k0 + t];
    __syncthreads();
    float acc[SS];
#pragma unroll
    for (int s = 0; s < SS; s++) {
        float ac = 0.f, as_ = 0.f;
#pragma unroll
        for (int c = 0; c < CC; c++) ac  += sCur[s*CC+c]  * T0[c*128+t];
#pragma unroll
        for (int j = 0; j < SS; j++) as_ += sSlot[s*SS+j] * T1[j*128+t];
        acc[s] = invRowCur[s]*ac + invRowSlot[s]*as_;
    }
    __syncthreads();

    // ---- Phase B2: slots_u += rel_cls blk3 + rel_slots blk4, then write ----
    for (int c = 0; c < CC; c++)
        T0[c*128 + t] = g_Y[((size_t)NSLOT + (size_t)b*CC + c) * NW + 3*HH + k0 + t];
    for (int s = 0; s < SS; s++)
        T1[s*128 + t] = g_Y[(size_t)(b*SS + s) * NW + 4*HH + k0 + t];
    __syncthreads();
#pragma unroll
    for (int s = 0; s < SS; s++) {
        float ac = 0.f, as_ = 0.f;
#pragma unroll
        for (int c = 0; c < CC; c++) ac  += sLast[s*CC+c] * T0[c*128+t];
#pragma unroll
        for (int j = 0; j < SS; j++) as_ += sDom[s*SS+j]  * T1[j*128+t];
        acc[s] += invRowLast[s]*ac + invRowDom[s]*as_;
        size_t srow = (size_t)(b*SS + s);
        g_U[srow * HH + k0 + t] = g_Y[srow * NW + k0 + t] + acc[s];
    }
}

// ---------------- SGEMM 2: gate = sigmoid(U@Wg0 + X@Wg1 + bg), fused residual update ----------------
__global__ void __launch_bounds__(256) k_gemm_gate(int layer,
                                                   const float* __restrict__ Wg,
                                                   const float* __restrict__ bg) {
    const float* __restrict__ Xold = layer ? g_X1 : g_X0;
    float* __restrict__ Xnew       = layer ? g_X0 : g_X1;
    const int bn = blockIdx.x * 128;   // col in HH
    const int bm = blockIdx.y * 128;
    __shared__ float As[16][128];
    __shared__ float Bs[16][128];
    const int tid = threadIdx.x;
    const int tx = tid & 15, ty = tid >> 4;

    float acc[8][8];
#pragma unroll
    for (int i = 0; i < 8; i++)
#pragma unroll
        for (int j = 0; j < 8; j++) acc[i][j] = 0.f;

    for (int half = 0; half < 2; half++) {
        const float* __restrict__ A = half ? Xold : g_U;
        const float* __restrict__ W = Wg + (size_t)half * HH * HH;
        for (int k0 = 0; k0 < HH; k0 += 16) {
#pragma unroll
            for (int l = 0; l < 2; l++) {
                int idx = tid + l * 256;
                int ar = idx >> 2, ak = (idx & 3) << 2;
                float4 va = *(const float4*)(A + (size_t)(bm + ar) * HH + k0 + ak);
                As[ak+0][ar] = va.x; As[ak+1][ar] = va.y;
                As[ak+2][ar] = va.z; As[ak+3][ar] = va.w;
                int brr = idx >> 5, bc = (idx & 31) << 2;
                float4 vb = *(const float4*)(W + (size_t)(k0 + brr) * HH + bn + bc);
                *(float4*)&Bs[brr][bc] = vb;
            }
            __syncthreads();
#pragma unroll
            for (int k = 0; k < 16; k++) {
                float a[8], b[8];
#pragma unroll
                for (int j = 0; j < 8; j++) { a[j] = As[k][ty*8+j]; b[j] = Bs[k][tx*8+j]; }
#pragma unroll
                for (int i = 0; i < 8; i++)
#pragma unroll
                    for (int j = 0; j < 8; j++) acc[i][j] += a[i] * b[j];
            }
            __syncthreads();
        }
    }
#pragma unroll
    for (int i = 0; i < 8; i++) {
        size_t row = (size_t)(bm + ty*8 + i);
#pragma unroll
        for (int j = 0; j < 8; j++) {
            int col = bn + tx*8 + j;
            float g = 1.f / (1.f + expf(-(acc[i][j] + bg[col])));
            float u = g_U [row * HH + col];
            float x = Xold[row * HH + col];
            Xnew[row * HH + col] = fmaxf(u, 0.f) * g + x * (1.f - g);
        }
    }
}

// ---------------- output: cls[:,1:,:] from final state (in g_X0 after layer 1) ----------------
__global__ void k_out(float* __restrict__ out) {
    size_t i = (size_t)blockIdx.x * blockDim.x + threadIdx.x;
    const size_t total = (size_t)BB * 15 * HH;
    if (i >= total) return;
    int k = (int)(i % HH);
    size_t r = i / HH;
    int c = (int)(r % 15) + 1;
    int b = (int)(r / 15);
    out[i] = g_X0[((size_t)NSLOT + (size_t)b*CC + c) * HH + k];
}

// ---------------- launch ----------------
extern "C" void kernel_launch(void* const* d_in, const int* in_sizes, int n_in,
                              void* d_out, int out_size) {
    const float* slots  = (const float*)d_in[0];
    const float* cls    = (const float*)d_in[1];
    const float* a_cur  = (const float*)d_in[2];
    const float* a_slot = (const float*)d_in[3];
    const float* a_last = (const float*)d_in[4];
    const float* a_dom  = (const float*)d_in[5];
    const float* W_r    = (const float*)d_in[6];
    const float* b_r    = (const float*)d_in[7];
    const float* W_s    = (const float*)d_in[8];
    const float* b_s    = (const float*)d_in[9];
    const float* W_g    = (const float*)d_in[10];
    const float* b_g    = (const float*)d_in[11];
    float* out = (float*)d_out;

    {
        size_t n = (size_t)NSLOT * HH;   // covers cls part too (smaller)
        k_init<<<(unsigned)((n + 1023) / 1024), 1024>>>(slots, cls);
    }
    {
        size_t n = (size_t)HH * NW;
        k_pack<<<(unsigned)((n + 1023) / 1024), 1024>>>(W_s, b_s, W_r, b_r);
    }
    for (int layer = 0; layer < 2; layer++) {
        k_gemm_proj<<<dim3(NW/128, NROW/128), 256>>>(layer);
        k_mix<<<dim3(BB, HH/128), 128>>>(a_cur, a_slot, a_last, a_dom);
        k_gemm_gate<<<dim3(HH/128, NROW/128), 256>>>(layer, W_g, b_g);
    }
    {
        size_t n = (size_t)BB * 15 * HH;
        k_out<<<(unsigned)((n + 255) / 256), 256>>>(out);
    }
}

// round 3
// speedup vs baseline: 2.0166x; 2.0166x over previous
#include <cuda_runtime.h>
#include <cuda_bf16.h>
#include <math.h>
#include <stdint.h>

#define BB 512
#define SS 30
#define CC 16
#define HH 768
#define NW 3840
#define NSLOT 15360
#define NCLS 8192
#define NROW 23552
#define EPSV 1e-5f

// GEMM tiling
#define BM 128
#define BN 128
#define BK 32
#define NTHREADS 256
#define PITCH 80          // bytes per smem row (32 bf16 = 64B data + 16B pad)
#define OFF_AH 0
#define OFF_AL 10240
#define OFF_BH 20480
#define OFF_BL 30720
#define STAGE  40960
#define SMEM_TOTAL (2*STAGE)

// ---------------- scratch (__device__ globals; no allocations) ----------------
__device__ __align__(128) __nv_bfloat16 g_Xhi[2][(size_t)NROW*HH];
__device__ __align__(128) __nv_bfloat16 g_Xlo[2][(size_t)NROW*HH];
__device__ __align__(128) __nv_bfloat16 g_Uhi[(size_t)NROW*HH];
__device__ __align__(128) __nv_bfloat16 g_Ulo[(size_t)NROW*HH];
__device__ __align__(128) float g_Y[(size_t)NROW*NW];
__device__ __align__(128) __nv_bfloat16 g_Wthi[(size_t)NW*HH];    // [NW][HH]  (B^T for proj)
__device__ __align__(128) __nv_bfloat16 g_Wtlo[(size_t)NW*HH];
__device__ __align__(128) __nv_bfloat16 g_Wgthi[(size_t)HH*2*HH]; // [HH][2*HH] (B^T for gate)
__device__ __align__(128) __nv_bfloat16 g_Wgtlo[(size_t)HH*2*HH];
__device__ float g_bcat[NW];

// ---------------- PTX helpers ----------------
__device__ __forceinline__ uint32_t s2u(const void* p) {
    uint32_t a;
    asm("{ .reg .u64 t; cvta.to.shared.u64 t, %1; cvt.u32.u64 %0, t; }" : "=r"(a) : "l"(p));
    return a;
}
__device__ __forceinline__ void cpa16(uint32_t s, const void* g) {
    asm volatile("cp.async.cg.shared.global [%0], [%1], 16;" :: "r"(s), "l"(g));
}
__device__ __forceinline__ void ldsm_x4(uint32_t addr, uint32_t* r) {
    asm volatile("ldmatrix.sync.aligned.m8n8.x4.shared.b16 {%0,%1,%2,%3}, [%4];"
        : "=r"(r[0]), "=r"(r[1]), "=r"(r[2]), "=r"(r[3]) : "r"(addr));
}
__device__ __forceinline__ void ldsm_x2(uint32_t addr, uint32_t* r) {
    asm volatile("ldmatrix.sync.aligned.m8n8.x2.shared.b16 {%0,%1}, [%2];"
        : "=r"(r[0]), "=r"(r[1]) : "r"(addr));
}
__device__ __forceinline__ void mma16816(float* d, const uint32_t* a, const uint32_t* b) {
    asm volatile("mma.sync.aligned.m16n8k16.row.col.f32.bf16.bf16.f32 "
        "{%0,%1,%2,%3}, {%4,%5,%6,%7}, {%8,%9}, {%0,%1,%2,%3};"
        : "+f"(d[0]), "+f"(d[1]), "+f"(d[2]), "+f"(d[3])
        : "r"(a[0]), "r"(a[1]), "r"(a[2]), "r"(a[3]), "r"(b[0]), "r"(b[1]));
}

__device__ __forceinline__ void split2(float x, __nv_bfloat16& hi, __nv_bfloat16& lo) {
    hi = __float2bfloat16(x);
    lo = __float2bfloat16(x - __bfloat162float(hi));
}

// ---------------- init: X[0] = split(concat(slots, cls)) ----------------
__global__ void k_init(const float* __restrict__ slots, const float* __restrict__ cls) {
    size_t i = (size_t)blockIdx.x * blockDim.x + threadIdx.x;
    if (i >= (size_t)NROW * HH) return;
    const size_t n0 = (size_t)NSLOT * HH;
    float v = (i < n0) ? slots[i] : cls[i - n0];
    split2(v, g_Xhi[0][i], g_Xlo[0][i]);
}

// ---------------- pack: Wt[j][h] = Wcat[h][j] split; bcat ----------------
__global__ void k_packW(const float* __restrict__ Ws, const float* __restrict__ bs,
                        const float* __restrict__ Wr, const float* __restrict__ br) {
    size_t i = (size_t)blockIdx.x * blockDim.x + threadIdx.x;
    if (i < (size_t)NW * HH) {
        int j = (int)(i / HH);           // output col 0..NW-1
        int h = (int)(i % HH);           // input dim
        int p = j / HH;                  // 0..4
        int n = j % HH;
        float w = (p == 0) ? Ws[(size_t)h * HH + n]
                           : Wr[((size_t)(p - 1) * HH + h) * HH + n];
        split2(w, g_Wthi[i], g_Wtlo[i]);
    }
    if (i < NW) {
        int p = (int)(i / HH), n = (int)(i % HH);
        g_bcat[i] = (p == 0) ? bs[n] : br[(size_t)(p - 1) * HH + n];
    }
}
__global__ void k_packG(const float* __restrict__ Wg) {
    size_t i = (size_t)blockIdx.x * blockDim.x + threadIdx.x;
    if (i >= (size_t)HH * 2 * HH) return;
    int j = (int)(i / (2 * HH));   // output col 0..767
    int k = (int)(i % (2 * HH));   // input dim 0..1535
    split2(Wg[(size_t)k * HH + j], g_Wgthi[i], g_Wgtlo[i]);
}

// ---------------- stage loader: 128x32 bf16 tiles (A hi/lo + B hi/lo) ----------------
__device__ __forceinline__ void load_tile(
    uint32_t stg, int tid,
    const __nv_bfloat16* __restrict__ Ah, const __nv_bfloat16* __restrict__ Al,
    size_t a_row0, int a_ld, int ak,
    const __nv_bfloat16* __restrict__ Bh, const __nv_bfloat16* __restrict__ Bl,
    size_t b_row0, int b_ld, int bk) {
#pragma unroll
    for (int t = 0; t < 2; t++) {
        int id = tid + t * NTHREADS;
        int row = id >> 2, c = id & 3;
        uint32_t so = (uint32_t)(row * PITCH + c * 16);
        size_t ga = (a_row0 + row) * (size_t)a_ld + ak + c * 8;
        cpa16(stg + OFF_AH + so, Ah + ga);
        cpa16(stg + OFF_AL + so, Al + ga);
        size_t gb = (b_row0 + row) * (size_t)b_ld + bk + c * 8;
        cpa16(stg + OFF_BH + so, Bh + gb);
        cpa16(stg + OFF_BL + so, Bl + gb);
    }
}

// ---------------- per-BK-tile compute: 3-term split-bf16 MMA ----------------
__device__ __forceinline__ void compute_tile(uint32_t stg, uint32_t aoff, uint32_t boff,
                                             float acc[4][4][4]) {
#pragma unroll
    for (int kk = 0; kk < 2; kk++) {
        uint32_t ah[4][4], al[4][4], bh[4][2], bl[4][2];
#pragma unroll
        for (int mt = 0; mt < 4; mt++) {
            uint32_t ad = stg + OFF_AH + aoff + mt * (16 * PITCH) + kk * 32;
            ldsm_x4(ad, ah[mt]);
            ldsm_x4(ad + (OFF_AL - OFF_AH), al[mt]);
        }
#pragma unroll
        for (int nt = 0; nt < 4; nt++) {
            uint32_t bd = stg + OFF_BH + boff + nt * (8 * PITCH) + kk * 32;
            ldsm_x2(bd, bh[nt]);
            ldsm_x2(bd + (OFF_BL - OFF_BH), bl[nt]);
        }
#pragma unroll
        for (int mt = 0; mt < 4; mt++)
#pragma unroll
            for (int nt = 0; nt < 4; nt++) {
                mma16816(acc[mt][nt], ah[mt], bh[nt]);
                mma16816(acc[mt][nt], ah[mt], bl[nt]);
                mma16816(acc[mt][nt], al[mt], bh[nt]);
            }
    }
}

// ---------------- GEMM 1: Y = X @ Wcat + bcat ----------------
__global__ void __launch_bounds__(NTHREADS, 1) k_gemm_proj(int layer) {
    extern __shared__ __align__(128) char smem[];
    uint32_t sb = s2u(smem);
    const int tid = threadIdx.x, lane = tid & 31, wid = tid >> 5;
    const int wm = wid >> 2, wn = wid & 3;
    const int bn = blockIdx.x * BN;
    const size_t bm = (size_t)blockIdx.y * BM;
    const __nv_bfloat16* __restrict__ Ah = g_Xhi[layer & 1];
    const __nv_bfloat16* __restrict__ Al = g_Xlo[layer & 1];

    float acc[4][4][4];
#pragma unroll
    for (int a = 0; a < 4; a++)
#pragma unroll
        for (int b = 0; b < 4; b++)
#pragma unroll
            for (int c = 0; c < 4; c++) acc[a][b][c] = 0.f;

    const uint32_t aoff = (uint32_t)((wm * 64 + (lane & 15)) * PITCH + ((lane >> 4) * 16));
    const uint32_t boff = (uint32_t)((wn * 32 + (lane & 7)) * PITCH + (((lane >> 3) & 1) * 16));

    load_tile(sb, tid, Ah, Al, bm, HH, 0, g_Wthi, g_Wtlo, bn, HH, 0);
    asm volatile("cp.async.commit_group;");
    for (int kt = 0; kt < 24; kt++) {
        __syncthreads();                       // buffer (kt+1)&1 free for overwrite
        if (kt + 1 < 24)
            load_tile(sb + ((kt + 1) & 1) * STAGE, tid, Ah, Al, bm, HH, (kt + 1) * BK,
                      g_Wthi, g_Wtlo, bn, HH, (kt + 1) * BK);
        asm volatile("cp.async.commit_group;");
        asm volatile("cp.async.wait_group 1;" ::: "memory");
        __syncthreads();
        compute_tile(sb + (kt & 1) * STAGE, aoff, boff, acc);
    }

    const int gid = lane >> 2, tig = lane & 3;
#pragma unroll
    for (int mt = 0; mt < 4; mt++) {
        size_t r0 = bm + wm * 64 + mt * 16 + gid;
#pragma unroll
        for (int nt = 0; nt < 4; nt++) {
            int col = bn + wn * 32 + nt * 8 + tig * 2;
            float2 bia = *(const float2*)(g_bcat + col);
            float2 v0 = make_float2(acc[mt][nt][0] + bia.x, acc[mt][nt][1] + bia.y);
            float2 v1 = make_float2(acc[mt][nt][2] + bia.x, acc[mt][nt][3] + bia.y);
            *(float2*)(g_Y + r0 * NW + col) = v0;
            *(float2*)(g_Y + (r0 + 8) * NW + col) = v1;
        }
    }
}

// ---------------- GEMM 2: gate = sigmoid([U|X] @ Wg + bg), fused residual ----------------
__global__ void __launch_bounds__(NTHREADS, 1) k_gemm_gate(int layer, const float* __restrict__ bg) {
    extern __shared__ __align__(128) char smem[];
    uint32_t sb = s2u(smem);
    const int tid = threadIdx.x, lane = tid & 31, wid = tid >> 5;
    const int wm = wid >> 2, wn = wid & 3;
    const int bn = blockIdx.x * BN;
    const size_t bm = (size_t)blockIdx.y * BM;
    const __nv_bfloat16* __restrict__ Xh = g_Xhi[layer & 1];
    const __nv_bfloat16* __restrict__ Xl = g_Xlo[layer & 1];
    __nv_bfloat16* __restrict__ Nh = g_Xhi[(layer + 1) & 1];
    __nv_bfloat16* __restrict__ Nl = g_Xlo[(layer + 1) & 1];

    float acc[4][4][4];
#pragma unroll
    for (int a = 0; a < 4; a++)
#pragma unroll
        for (int b = 0; b < 4; b++)
#pragma unroll
            for (int c = 0; c < 4; c++) acc[a][b][c] = 0.f;

    const uint32_t aoff = (uint32_t)((wm * 64 + (lane & 15)) * PITCH + ((lane >> 4) * 16));
    const uint32_t boff = (uint32_t)((wn * 32 + (lane & 7)) * PITCH + (((lane >> 3) & 1) * 16));

    load_tile(sb, tid, g_Uhi, g_Ulo, bm, HH, 0, g_Wgthi, g_Wgtlo, bn, 2 * HH, 0);
    asm volatile("cp.async.commit_group;");
    for (int kt = 0; kt < 48; kt++) {
        __syncthreads();
        if (kt + 1 < 48) {
            int nk = kt + 1;
            const __nv_bfloat16* ah = (nk < 24) ? g_Uhi : Xh;
            const __nv_bfloat16* al = (nk < 24) ? g_Ulo : Xl;
            int ak = (nk < 24) ? nk * BK : (nk - 24) * BK;
            load_tile(sb + (nk & 1) * STAGE, tid, ah, al, bm, HH, ak,
                      g_Wgthi, g_Wgtlo, bn, 2 * HH, nk * BK);
        }
        asm volatile("cp.async.commit_group;");
        asm volatile("cp.async.wait_group 1;" ::: "memory");
        __syncthreads();
        compute_tile(sb + (kt & 1) * STAGE, aoff, boff, acc);
    }

    const int gid = lane >> 2, tig = lane & 3;
#pragma unroll
    for (int mt = 0; mt < 4; mt++) {
        size_t r0 = bm + wm * 64 + mt * 16 + gid;
#pragma unroll
        for (int nt = 0; nt < 4; nt++) {
            int col = bn + wn * 32 + nt * 8 + tig * 2;
            float2 bia = *(const float2*)(bg + col);
#pragma unroll
            for (int h = 0; h < 2; h++) {
                size_t row = r0 + h * 8;
                size_t base = row * HH + col;
                float rr0 = acc[mt][nt][h * 2 + 0] + bia.x;
                float rr1 = acc[mt][nt][h * 2 + 1] + bia.y;
                float g0 = 1.f / (1.f + __expf(-rr0));
                float g1 = 1.f / (1.f + __expf(-rr1));
                float2 uh = __bfloat1622float2(*(const __nv_bfloat162*)(g_Uhi + base));
                float2 ul = __bfloat1622float2(*(const __nv_bfloat162*)(g_Ulo + base));
                float2 xh = __bfloat1622float2(*(const __nv_bfloat162*)(Xh + base));
                float2 xl = __bfloat1622float2(*(const __nv_bfloat162*)(Xl + base));
                float u0 = uh.x + ul.x, u1 = uh.y + ul.y;
                float x0 = xh.x + xl.x, x1 = xh.y + xl.y;
                float n0 = fmaxf(u0, 0.f) * g0 + x0 * (1.f - g0);
                float n1 = fmaxf(u1, 0.f) * g1 + x1 * (1.f - g1);
                __nv_bfloat16 h0, l0, h1, l1;
                split2(n0, h0, l0);
                split2(n1, h1, l1);
                *(__nv_bfloat162*)(Nh + base) = __nv_bfloat162(h0, h1);
                *(__nv_bfloat162*)(Nl + base) = __nv_bfloat162(l0, l1);
            }
        }
    }
}

// ---------------- mixing: U = Y[:,blk0] + normalized attention messages ----------------
__global__ void __launch_bounds__(128) k_mix(const float* __restrict__ a_cur,
                                             const float* __restrict__ a_slot,
                                             const float* __restrict__ a_last,
                                             const float* __restrict__ a_dom) {
    const int b = blockIdx.x;
    const int k0 = blockIdx.y * 128;
    const int t = threadIdx.x;

    __shared__ float sCur[SS*CC], sLast[SS*CC], sSlot[SS*SS], sDom[SS*SS];
    __shared__ float invColCur[CC], invColLast[CC];
    __shared__ float invRowCur[SS], invRowSlot[SS], invRowLast[SS], invRowDom[SS];
    __shared__ float T0[SS*128];
    __shared__ float T1[SS*128];

    for (int i = t; i < SS*CC; i += 128) {
        sCur[i]  = a_cur [(size_t)b*SS*CC + i];
        sLast[i] = a_last[(size_t)b*SS*CC + i];
    }
    for (int i = t; i < SS*SS; i += 128) {
        sSlot[i] = a_slot[(size_t)b*SS*SS + i];
        sDom[i]  = a_dom [(size_t)b*SS*SS + i];
    }
    __syncthreads();
    if (t < CC) {
        float s1 = 0.f, s2 = 0.f;
        for (int s = 0; s < SS; s++) { s1 += sCur[s*CC+t]; s2 += sLast[s*CC+t]; }
        invColCur[t]  = 1.f / (s1 + EPSV);
        invColLast[t] = 1.f / (s2 + EPSV);
    } else if (t >= 32 && t < 32 + SS) {
        int s = t - 32; float s1 = 0.f, s2 = 0.f;
        for (int c = 0; c < CC; c++) { s1 += sCur[s*CC+c]; s2 += sLast[s*CC+c]; }
        invRowCur[s]  = 1.f / (s1 + EPSV);
        invRowLast[s] = 1.f / (s2 + EPSV);
    } else if (t >= 64 && t < 64 + SS) {
        int s = t - 64; float s1 = 0.f, s2 = 0.f;
        for (int j = 0; j < SS; j++) { s1 += sSlot[s*SS+j]; s2 += sDom[s*SS+j]; }
        invRowSlot[s] = 1.f / (s1 + EPSV);
        invRowDom[s]  = 1.f / (s2 + EPSV);
    }
    __syncthreads();

    // Phase A: cls rows
    for (int s = 0; s < SS; s++) {
        size_t base = (size_t)(b*SS + s) * NW + k0 + t;
        T0[s*128 + t] = g_Y[base + 1*HH];
        T1[s*128 + t] = g_Y[base + 3*HH];
    }
    __syncthreads();
    for (int c = 0; c < CC; c++) {
        float a1 = 0.f, a3 = 0.f;
#pragma unroll
        for (int s = 0; s < SS; s++) {
            a1 += sCur[s*CC+c]  * T0[s*128+t];
            a3 += sLast[s*CC+c] * T1[s*128+t];
        }
        size_t crow = (size_t)NSLOT + (size_t)b*CC + c;
        float v = g_Y[crow * NW + k0 + t] + invColCur[c]*a1 + invColLast[c]*a3;
        size_t idx = crow * HH + k0 + t;
        split2(v, g_Uhi[idx], g_Ulo[idx]);
    }
    __syncthreads();

    // Phase B1
    for (int c = 0; c < CC; c++)
        T0[c*128 + t] = g_Y[((size_t)NSLOT + (size_t)b*CC + c) * NW + 1*HH + k0 + t];
    for (int s = 0; s < SS; s++)
        T1[s*128 + t] = g_Y[(size_t)(b*SS + s) * NW + 2*HH + k0 + t];
    __syncthreads();
    float acc[SS];
#pragma unroll
    for (int s = 0; s < SS; s++) {
        float ac = 0.f, as_ = 0.f;
#pragma unroll
        for (int c = 0; c < CC; c++) ac  += sCur[s*CC+c]  * T0[c*128+t];
#pragma unroll
        for (int j = 0; j < SS; j++) as_ += sSlot[s*SS+j] * T1[j*128+t];
        acc[s] = invRowCur[s]*ac + invRowSlot[s]*as_;
    }
    __syncthreads();

    // Phase B2
    for (int c = 0; c < CC; c++)
        T0[c*128 + t] = g_Y[((size_t)NSLOT + (size_t)b*CC + c) * NW + 3*HH + k0 + t];
    for (int s = 0; s < SS; s++)
        T1[s*128 + t] = g_Y[(size_t)(b*SS + s) * NW + 4*HH + k0 + t];
    __syncthreads();
#pragma unroll
    for (int s = 0; s < SS; s++) {
        float ac = 0.f, as_ = 0.f;
#pragma unroll
        for (int c = 0; c < CC; c++) ac  += sLast[s*CC+c] * T0[c*128+t];
#pragma unroll
        for (int j = 0; j < SS; j++) as_ += sDom[s*SS+j]  * T1[j*128+t];
        acc[s] += invRowLast[s]*ac + invRowDom[s]*as_;
        size_t srow = (size_t)(b*SS + s);
        float v = g_Y[srow * NW + k0 + t] + acc[s];
        size_t idx = srow * HH + k0 + t;
        split2(v, g_Uhi[idx], g_Ulo[idx]);
    }
}

// ---------------- output ----------------
__global__ void k_out(float* __restrict__ out) {
    size_t i = (size_t)blockIdx.x * blockDim.x + threadIdx.x;
    const size_t total = (size_t)BB * 15 * HH;
    if (i >= total) return;
    int k = (int)(i % HH);
    size_t r = i / HH;
    int c = (int)(r % 15) + 1;
    int b = (int)(r / 15);
    size_t idx = ((size_t)NSLOT + (size_t)b*CC + c) * HH + k;
    out[i] = __bfloat162float(g_Xhi[0][idx]) + __bfloat162float(g_Xlo[0][idx]);
}

// ---------------- launch ----------------
extern "C" void kernel_launch(void* const* d_in, const int* in_sizes, int n_in,
                              void* d_out, int out_size) {
    const float* slots  = (const float*)d_in[0];
    const float* cls    = (const float*)d_in[1];
    const float* a_cur  = (const float*)d_in[2];
    const float* a_slot = (const float*)d_in[3];
    const float* a_last = (const float*)d_in[4];
    const float* a_dom  = (const float*)d_in[5];
    const float* W_r    = (const float*)d_in[6];
    const float* b_r    = (const float*)d_in[7];
    const float* W_s    = (const float*)d_in[8];
    const float* b_s    = (const float*)d_in[9];
    const float* W_g    = (const float*)d_in[10];
    const float* b_g    = (const float*)d_in[11];
    float* out = (float*)d_out;

    cudaFuncSetAttribute(k_gemm_proj, cudaFuncAttributeMaxDynamicSharedMemorySize, SMEM_TOTAL);
    cudaFuncSetAttribute(k_gemm_gate, cudaFuncAttributeMaxDynamicSharedMemorySize, SMEM_TOTAL);

    {
        size_t n = (size_t)NROW * HH;
        k_init<<<(unsigned)((n + 1023) / 1024), 1024>>>(slots, cls);
    }
    {
        size_t n = (size_t)NW * HH;
        k_packW<<<(unsigned)((n + 1023) / 1024), 1024>>>(W_s, b_s, W_r, b_r);
    }
    {
        size_t n = (size_t)HH * 2 * HH;
        k_packG<<<(unsigned)((n + 1023) / 1024), 1024>>>(W_g);
    }
    for (int layer = 0; layer < 2; layer++) {
        k_gemm_proj<<<dim3(NW/BN, NROW/BM), NTHREADS, SMEM_TOTAL>>>(layer);
        k_mix<<<dim3(BB, HH/128), 128>>>(a_cur, a_slot, a_last, a_dom);
        k_gemm_gate<<<dim3(HH/BN, NROW/BM), NTHREADS, SMEM_TOTAL>>>(layer, b_g);
    }
    {
        size_t n = (size_t)BB * 15 * HH;
        k_out<<<(unsigned)((n + 255) / 256), 256>>>(out);
    }
}

// round 4
// speedup vs baseline: 2.4599x; 1.2199x over previous
#include <cuda_runtime.h>
#include <cuda_bf16.h>
#include <math.h>
#include <stdint.h>

#define BB 512
#define SS 30
#define CC 16
#define HH 768
#define NW 3840
#define NSLOT 15360
#define NCLS 8192
#define NROW 23552
#define EPSV 1e-5f

// GEMM tiling
#define BM 128
#define BN 128
#define BK 64
#define NTHREADS 256
#define PITCH 144         // bytes per smem row (64 bf16 = 128B data + 16B pad)
#define TILE_BYTES (128*PITCH)          // 18432
#define OFF_AH 0
#define OFF_AL TILE_BYTES
#define OFF_BH (2*TILE_BYTES)
#define OFF_BL (3*TILE_BYTES)
#define STAGE  (4*TILE_BYTES)           // 73728
#define SMEM_TOTAL (2*STAGE)            // 147456

// ---------------- scratch (__device__ globals; no allocations) ----------------
__device__ __align__(128) __nv_bfloat16 g_Xhi[2][(size_t)NROW*HH];
__device__ __align__(128) __nv_bfloat16 g_Xlo[2][(size_t)NROW*HH];
__device__ __align__(128) __nv_bfloat16 g_Uhi[(size_t)NROW*HH];
__device__ __align__(128) __nv_bfloat16 g_Ulo[(size_t)NROW*HH];
__device__ __align__(128) float g_Y[(size_t)NROW*NW];
__device__ __align__(128) __nv_bfloat16 g_Wthi[(size_t)NW*HH];    // [NW][HH]  (B^T for proj)
__device__ __align__(128) __nv_bfloat16 g_Wtlo[(size_t)NW*HH];
__device__ __align__(128) __nv_bfloat16 g_Wgthi[(size_t)HH*2*HH]; // [HH][2*HH] (B^T for gate)
__device__ __align__(128) __nv_bfloat16 g_Wgtlo[(size_t)HH*2*HH];
__device__ float g_bcat[NW];

// ---------------- PTX helpers ----------------
__device__ __forceinline__ uint32_t s2u(const void* p) {
    uint32_t a;
    asm("{ .reg .u64 t; cvta.to.shared.u64 t, %1; cvt.u32.u64 %0, t; }" : "=r"(a) : "l"(p));
    return a;
}
__device__ __forceinline__ void cpa16(uint32_t s, const void* g) {
    asm volatile("cp.async.cg.shared.global [%0], [%1], 16;" :: "r"(s), "l"(g));
}
__device__ __forceinline__ void ldsm_x4(uint32_t addr, uint32_t* r) {
    asm volatile("ldmatrix.sync.aligned.m8n8.x4.shared.b16 {%0,%1,%2,%3}, [%4];"
        : "=r"(r[0]), "=r"(r[1]), "=r"(r[2]), "=r"(r[3]) : "r"(addr));
}
__device__ __forceinline__ void ldsm_x2(uint32_t addr, uint32_t* r) {
    asm volatile("ldmatrix.sync.aligned.m8n8.x2.shared.b16 {%0,%1}, [%2];"
        : "=r"(r[0]), "=r"(r[1]) : "r"(addr));
}
__device__ __forceinline__ void mma16816(float* d, const uint32_t* a, const uint32_t* b) {
    asm volatile("mma.sync.aligned.m16n8k16.row.col.f32.bf16.bf16.f32 "
        "{%0,%1,%2,%3}, {%4,%5,%6,%7}, {%8,%9}, {%0,%1,%2,%3};"
        : "+f"(d[0]), "+f"(d[1]), "+f"(d[2]), "+f"(d[3])
        : "r"(a[0]), "r"(a[1]), "r"(a[2]), "r"(a[3]), "r"(b[0]), "r"(b[1]));
}

__device__ __forceinline__ void split2(float x, __nv_bfloat16& hi, __nv_bfloat16& lo) {
    hi = __float2bfloat16(x);
    lo = __float2bfloat16(x - __bfloat162float(hi));
}

// ---------------- init / pack ----------------
__global__ void k_init(const float* __restrict__ slots, const float* __restrict__ cls) {
    size_t i = (size_t)blockIdx.x * blockDim.x + threadIdx.x;
    if (i >= (size_t)NROW * HH) return;
    const size_t n0 = (size_t)NSLOT * HH;
    float v = (i < n0) ? slots[i] : cls[i - n0];
    split2(v, g_Xhi[0][i], g_Xlo[0][i]);
}
__global__ void k_packW(const float* __restrict__ Ws, const float* __restrict__ bs,
                        const float* __restrict__ Wr, const float* __restrict__ br) {
    size_t i = (size_t)blockIdx.x * blockDim.x + threadIdx.x;
    if (i < (size_t)NW * HH) {
        int j = (int)(i / HH);
        int h = (int)(i % HH);
        int p = j / HH;
        int n = j % HH;
        float w = (p == 0) ? Ws[(size_t)h * HH + n]
                           : Wr[((size_t)(p - 1) * HH + h) * HH + n];
        split2(w, g_Wthi[i], g_Wtlo[i]);
    }
    if (i < NW) {
        int p = (int)(i / HH), n = (int)(i % HH);
        g_bcat[i] = (p == 0) ? bs[n] : br[(size_t)(p - 1) * HH + n];
    }
}
__global__ void k_packG(const float* __restrict__ Wg) {
    size_t i = (size_t)blockIdx.x * blockDim.x + threadIdx.x;
    if (i >= (size_t)HH * 2 * HH) return;
    int j = (int)(i / (2 * HH));
    int k = (int)(i % (2 * HH));
    split2(Wg[(size_t)k * HH + j], g_Wgthi[i], g_Wgtlo[i]);
}

// ---------------- stage loader: 128x64 bf16 tiles (A hi/lo + B hi/lo) ----------------
__device__ __forceinline__ void load_tile(
    uint32_t stg, int tid,
    const __nv_bfloat16* __restrict__ Ah, const __nv_bfloat16* __restrict__ Al,
    size_t a_row0, int a_ld, int ak,
    const __nv_bfloat16* __restrict__ Bh, const __nv_bfloat16* __restrict__ Bl,
    size_t b_row0, int b_ld, int bk) {
#pragma unroll
    for (int t = 0; t < 4; t++) {
        int id = tid + t * NTHREADS;
        int row = id >> 3, c = id & 7;
        uint32_t so = (uint32_t)(row * PITCH + c * 16);
        size_t ga = (a_row0 + row) * (size_t)a_ld + ak + c * 8;
        cpa16(stg + OFF_AH + so, Ah + ga);
        cpa16(stg + OFF_AL + so, Al + ga);
        size_t gb = (b_row0 + row) * (size_t)b_ld + bk + c * 8;
        cpa16(stg + OFF_BH + so, Bh + gb);
        cpa16(stg + OFF_BL + so, Bl + gb);
    }
}

// ---------------- fragment load for one kk (16-wide K slice) ----------------
__device__ __forceinline__ void load_frags(uint32_t stg, uint32_t aoff, uint32_t boff, int kk,
                                           uint32_t ah[4][4], uint32_t al[4][4],
                                           uint32_t bh[4][2], uint32_t bl[4][2]) {
#pragma unroll
    for (int mt = 0; mt < 4; mt++) {
        uint32_t ad = stg + OFF_AH + aoff + mt * (16 * PITCH) + kk * 32;
        ldsm_x4(ad, ah[mt]);
        ldsm_x4(ad + (OFF_AL - OFF_AH), al[mt]);
    }
#pragma unroll
    for (int nt = 0; nt < 4; nt++) {
        uint32_t bd = stg + OFF_BH + boff + nt * (8 * PITCH) + kk * 32;
        ldsm_x2(bd, bh[nt]);
        ldsm_x2(bd + (OFF_BL - OFF_BH), bl[nt]);
    }
}

// ---------------- per-BK-tile compute: 3-term split-bf16, reg double-buffered ----------------
__device__ __forceinline__ void compute_tile(uint32_t stg, uint32_t aoff, uint32_t boff,
                                             float acc[4][4][4]) {
    uint32_t ah[2][4][4], al[2][4][4], bh[2][4][2], bl[2][4][2];
    load_frags(stg, aoff, boff, 0, ah[0], al[0], bh[0], bl[0]);
#pragma unroll
    for (int kk = 0; kk < 4; kk++) {
        int cur = kk & 1, nxt = cur ^ 1;
        if (kk < 3)
            load_frags(stg, aoff, boff, kk + 1, ah[nxt], al[nxt], bh[nxt], bl[nxt]);
#pragma unroll
        for (int mt = 0; mt < 4; mt++)
#pragma unroll
            for (int nt = 0; nt < 4; nt++) {
                mma16816(acc[mt][nt], ah[cur][mt], bh[cur][nt]);
                mma16816(acc[mt][nt], ah[cur][mt], bl[cur][nt]);
                mma16816(acc[mt][nt], al[cur][mt], bh[cur][nt]);
            }
    }
}

// ---------------- GEMM 1: Y = X @ Wcat + bcat ----------------
// cls_mode=0: rows [0,NSLOT), all 30 col blocks.
// cls_mode=1: rows [NSLOT,NROW), 18 col blocks remapped to p in {0,1,3}.
__global__ void __launch_bounds__(NTHREADS, 1) k_gemm_proj(int layer, int cls_mode) {
    extern __shared__ __align__(128) char smem[];
    uint32_t sb = s2u(smem);
    const int tid = threadIdx.x, lane = tid & 31, wid = tid >> 5;
    const int wm = wid >> 2, wn = wid & 3;
    int cb = blockIdx.x;
    if (cls_mode && cb >= 12) cb += 6;   // skip p=2 block (cols 1536..2303); cb 12..17 -> 18..23
    const int bn = cb * BN;
    const size_t bm = (cls_mode ? (size_t)NSLOT : 0) + (size_t)blockIdx.y * BM;
    const __nv_bfloat16* __restrict__ Ah = g_Xhi[layer & 1];
    const __nv_bfloat16* __restrict__ Al = g_Xlo[layer & 1];

    float acc[4][4][4];
#pragma unroll
    for (int a = 0; a < 4; a++)
#pragma unroll
        for (int b = 0; b < 4; b++)
#pragma unroll
            for (int c = 0; c < 4; c++) acc[a][b][c] = 0.f;

    const uint32_t aoff = (uint32_t)((wm * 64 + (lane & 15)) * PITCH + ((lane >> 4) * 16));
    const uint32_t boff = (uint32_t)((wn * 32 + (lane & 7)) * PITCH + (((lane >> 3) & 1) * 16));

    load_tile(sb, tid, Ah, Al, bm, HH, 0, g_Wthi, g_Wtlo, bn, HH, 0);
    asm volatile("cp.async.commit_group;");
    for (int kt = 0; kt < 12; kt++) {
        __syncthreads();
        if (kt + 1 < 12)
            load_tile(sb + ((kt + 1) & 1) * STAGE, tid, Ah, Al, bm, HH, (kt + 1) * BK,
                      g_Wthi, g_Wtlo, bn, HH, (kt + 1) * BK);
        asm volatile("cp.async.commit_group;");
        asm volatile("cp.async.wait_group 1;" ::: "memory");
        __syncthreads();
        compute_tile(sb + (kt & 1) * STAGE, aoff, boff, acc);
    }

    const int gid = lane >> 2, tig = lane & 3;
#pragma unroll
    for (int mt = 0; mt < 4; mt++) {
        size_t r0 = bm + wm * 64 + mt * 16 + gid;
#pragma unroll
        for (int nt = 0; nt < 4; nt++) {
            int col = bn + wn * 32 + nt * 8 + tig * 2;
            float2 bia = *(const float2*)(g_bcat + col);
            float2 v0 = make_float2(acc[mt][nt][0] + bia.x, acc[mt][nt][1] + bia.y);
            float2 v1 = make_float2(acc[mt][nt][2] + bia.x, acc[mt][nt][3] + bia.y);
            *(float2*)(g_Y + r0 * NW + col) = v0;
            *(float2*)(g_Y + (r0 + 8) * NW + col) = v1;
        }
    }
}

// ---------------- GEMM 2: gate = sigmoid([U|X] @ Wg + bg), fused residual ----------------
__global__ void __launch_bounds__(NTHREADS, 1) k_gemm_gate(int layer, const float* __restrict__ bg) {
    extern __shared__ __align__(128) char smem[];
    uint32_t sb = s2u(smem);
    const int tid = threadIdx.x, lane = tid & 31, wid = tid >> 5;
    const int wm = wid >> 2, wn = wid & 3;
    const int bn = blockIdx.x * BN;
    const size_t bm = (size_t)blockIdx.y * BM;
    const __nv_bfloat16* __restrict__ Xh = g_Xhi[layer & 1];
    const __nv_bfloat16* __restrict__ Xl = g_Xlo[layer & 1];
    __nv_bfloat16* __restrict__ Nh = g_Xhi[(layer + 1) & 1];
    __nv_bfloat16* __restrict__ Nl = g_Xlo[(layer + 1) & 1];

    float acc[4][4][4];
#pragma unroll
    for (int a = 0; a < 4; a++)
#pragma unroll
        for (int b = 0; b < 4; b++)
#pragma unroll
            for (int c = 0; c < 4; c++) acc[a][b][c] = 0.f;

    const uint32_t aoff = (uint32_t)((wm * 64 + (lane & 15)) * PITCH + ((lane >> 4) * 16));
    const uint32_t boff = (uint32_t)((wn * 32 + (lane & 7)) * PITCH + (((lane >> 3) & 1) * 16));

    load_tile(sb, tid, g_Uhi, g_Ulo, bm, HH, 0, g_Wgthi, g_Wgtlo, bn, 2 * HH, 0);
    asm volatile("cp.async.commit_group;");
    for (int kt = 0; kt < 24; kt++) {
        __syncthreads();
        if (kt + 1 < 24) {
            int nk = kt + 1;
            const __nv_bfloat16* ah = (nk < 12) ? g_Uhi : Xh;
            const __nv_bfloat16* al = (nk < 12) ? g_Ulo : Xl;
            int ak = (nk < 12) ? nk * BK : (nk - 12) * BK;
            load_tile(sb + (nk & 1) * STAGE, tid, ah, al, bm, HH, ak,
                      g_Wgthi, g_Wgtlo, bn, 2 * HH, nk * BK);
        }
        asm volatile("cp.async.commit_group;");
        asm volatile("cp.async.wait_group 1;" ::: "memory");
        __syncthreads();
        compute_tile(sb + (kt & 1) * STAGE, aoff, boff, acc);
    }

    const int gid = lane >> 2, tig = lane & 3;
#pragma unroll
    for (int mt = 0; mt < 4; mt++) {
        size_t r0 = bm + wm * 64 + mt * 16 + gid;
#pragma unroll
        for (int nt = 0; nt < 4; nt++) {
            int col = bn + wn * 32 + nt * 8 + tig * 2;
            float2 bia = *(const float2*)(bg + col);
#pragma unroll
            for (int h = 0; h < 2; h++) {
                size_t row = r0 + h * 8;
                size_t base = row * HH + col;
                float rr0 = acc[mt][nt][h * 2 + 0] + bia.x;
                float rr1 = acc[mt][nt][h * 2 + 1] + bia.y;
                float g0 = 1.f / (1.f + __expf(-rr0));
                float g1 = 1.f / (1.f + __expf(-rr1));
                float2 uh = __bfloat1622float2(*(const __nv_bfloat162*)(g_Uhi + base));
                float2 ul = __bfloat1622float2(*(const __nv_bfloat162*)(g_Ulo + base));
                float2 xh = __bfloat1622float2(*(const __nv_bfloat162*)(Xh + base));
                float2 xl = __bfloat1622float2(*(const __nv_bfloat162*)(Xl + base));
                float u0 = uh.x + ul.x, u1 = uh.y + ul.y;
                float x0 = xh.x + xl.x, x1 = xh.y + xl.y;
                float n0 = fmaxf(u0, 0.f) * g0 + x0 * (1.f - g0);
                float n1 = fmaxf(u1, 0.f) * g1 + x1 * (1.f - g1);
                __nv_bfloat16 h0, l0, h1, l1;
                split2(n0, h0, l0);
                split2(n1, h1, l1);
                *(__nv_bfloat162*)(Nh + base) = __nv_bfloat162(h0, h1);
                *(__nv_bfloat162*)(Nl + base) = __nv_bfloat162(l0, l1);
            }
        }
    }
}

// ---------------- mixing: U = Y[:,blk0] + normalized attention messages ----------------
__global__ void __launch_bounds__(128) k_mix(const float* __restrict__ a_cur,
                                             const float* __restrict__ a_slot,
                                             const float* __restrict__ a_last,
                                             const float* __restrict__ a_dom) {
    const int b = blockIdx.x;
    const int k0 = blockIdx.y * 128;
    const int t = threadIdx.x;

    __shared__ float sCur[SS*CC], sLast[SS*CC], sSlot[SS*SS], sDom[SS*SS];
    __shared__ float invColCur[CC], invColLast[CC];
    __shared__ float invRowCur[SS], invRowSlot[SS], invRowLast[SS], invRowDom[SS];
    __shared__ float T0[SS*128];
    __shared__ float T1[SS*128];

    for (int i = t; i < SS*CC; i += 128) {
        sCur[i]  = a_cur [(size_t)b*SS*CC + i];
        sLast[i] = a_last[(size_t)b*SS*CC + i];
    }
    for (int i = t; i < SS*SS; i += 128) {
        sSlot[i] = a_slot[(size_t)b*SS*SS + i];
        sDom[i]  = a_dom [(size_t)b*SS*SS + i];
    }
    __syncthreads();
    if (t < CC) {
        float s1 = 0.f, s2 = 0.f;
        for (int s = 0; s < SS; s++) { s1 += sCur[s*CC+t]; s2 += sLast[s*CC+t]; }
        invColCur[t]  = 1.f / (s1 + EPSV);
        invColLast[t] = 1.f / (s2 + EPSV);
    } else if (t >= 32 && t < 32 + SS) {
        int s = t - 32; float s1 = 0.f, s2 = 0.f;
        for (int c = 0; c < CC; c++) { s1 += sCur[s*CC+c]; s2 += sLast[s*CC+c]; }
        invRowCur[s]  = 1.f / (s1 + EPSV);
        invRowLast[s] = 1.f / (s2 + EPSV);
    } else if (t >= 64 && t < 64 + SS) {
        int s = t - 64; float s1 = 0.f, s2 = 0.f;
        for (int j = 0; j < SS; j++) { s1 += sSlot[s*SS+j]; s2 += sDom[s*SS+j]; }
        invRowSlot[s] = 1.f / (s1 + EPSV);
        invRowDom[s]  = 1.f / (s2 + EPSV);
    }
    __syncthreads();

    // Phase A: cls rows
    for (int s = 0; s < SS; s++) {
        size_t base = (size_t)(b*SS + s) * NW + k0 + t;
        T0[s*128 + t] = g_Y[base + 1*HH];
        T1[s*128 + t] = g_Y[base + 3*HH];
    }
    __syncthreads();
    for (int c = 0; c < CC; c++) {
        float a1 = 0.f, a3 = 0.f;
#pragma unroll
        for (int s = 0; s < SS; s++) {
            a1 += sCur[s*CC+c]  * T0[s*128+t];
            a3 += sLast[s*CC+c] * T1[s*128+t];
        }
        size_t crow = (size_t)NSLOT + (size_t)b*CC + c;
        float v = g_Y[crow * NW + k0 + t] + invColCur[c]*a1 + invColLast[c]*a3;
        size_t idx = crow * HH + k0 + t;
        split2(v, g_Uhi[idx], g_Ulo[idx]);
    }
    __syncthreads();

    // Phase B1
    for (int c = 0; c < CC; c++)
        T0[c*128 + t] = g_Y[((size_t)NSLOT + (size_t)b*CC + c) * NW + 1*HH + k0 + t];
    for (int s = 0; s < SS; s++)
        T1[s*128 + t] = g_Y[(size_t)(b*SS + s) * NW + 2*HH + k0 + t];
    __syncthreads();
    float acc[SS];
#pragma unroll
    for (int s = 0; s < SS; s++) {
        float ac = 0.f, as_ = 0.f;
#pragma unroll
        for (int c = 0; c < CC; c++) ac  += sCur[s*CC+c]  * T0[c*128+t];
#pragma unroll
        for (int j = 0; j < SS; j++) as_ += sSlot[s*SS+j] * T1[j*128+t];
        acc[s] = invRowCur[s]*ac + invRowSlot[s]*as_;
    }
    __syncthreads();

    // Phase B2
    for (int c = 0; c < CC; c++)
        T0[c*128 + t] = g_Y[((size_t)NSLOT + (size_t)b*CC + c) * NW + 3*HH + k0 + t];
    for (int s = 0; s < SS; s++)
        T1[s*128 + t] = g_Y[(size_t)(b*SS + s) * NW + 4*HH + k0 + t];
    __syncthreads();
#pragma unroll
    for (int s = 0; s < SS; s++) {
        float ac = 0.f, as_ = 0.f;
#pragma unroll
        for (int c = 0; c < CC; c++) ac  += sLast[s*CC+c] * T0[c*128+t];
#pragma unroll
        for (int j = 0; j < SS; j++) as_ += sDom[s*SS+j]  * T1[j*128+t];
        acc[s] += invRowLast[s]*ac + invRowDom[s]*as_;
        size_t srow = (size_t)(b*SS + s);
        float v = g_Y[srow * NW + k0 + t] + acc[s];
        size_t idx = srow * HH + k0 + t;
        split2(v, g_Uhi[idx], g_Ulo[idx]);
    }
}

// ---------------- output ----------------
__global__ void k_out(float* __restrict__ out) {
    size_t i = (size_t)blockIdx.x * blockDim.x + threadIdx.x;
    const size_t total = (size_t)BB * 15 * HH;
    if (i >= total) return;
    int k = (int)(i % HH);
    size_t r = i / HH;
    int c = (int)(r % 15) + 1;
    int b = (int)(r / 15);
    size_t idx = ((size_t)NSLOT + (size_t)b*CC + c) * HH + k;
    out[i] = __bfloat162float(g_Xhi[0][idx]) + __bfloat162float(g_Xlo[0][idx]);
}

// ---------------- launch ----------------
extern "C" void kernel_launch(void* const* d_in, const int* in_sizes, int n_in,
                              void* d_out, int out_size) {
    const float* slots  = (const float*)d_in[0];
    const float* cls    = (const float*)d_in[1];
    const float* a_cur  = (const float*)d_in[2];
    const float* a_slot = (const float*)d_in[3];
    const float* a_last = (const float*)d_in[4];
    const float* a_dom  = (const float*)d_in[5];
    const float* W_r    = (const float*)d_in[6];
    const float* b_r    = (const float*)d_in[7];
    const float* W_s    = (const float*)d_in[8];
    const float* b_s    = (const float*)d_in[9];
    const float* W_g    = (const float*)d_in[10];
    const float* b_g    = (const float*)d_in[11];
    float* out = (float*)d_out;

    cudaFuncSetAttribute(k_gemm_proj, cudaFuncAttributeMaxDynamicSharedMemorySize, SMEM_TOTAL);
    cudaFuncSetAttribute(k_gemm_gate, cudaFuncAttributeMaxDynamicSharedMemorySize, SMEM_TOTAL);

    {
        size_t n = (size_t)NROW * HH;
        k_init<<<(unsigned)((n + 1023) / 1024), 1024>>>(slots, cls);
    }
    {
        size_t n = (size_t)NW * HH;
        k_packW<<<(unsigned)((n + 1023) / 1024), 1024>>>(W_s, b_s, W_r, b_r);
    }
    {
        size_t n = (size_t)HH * 2 * HH;
        k_packG<<<(unsigned)((n + 1023) / 1024), 1024>>>(W_g);
    }
    for (int layer = 0; layer < 2; layer++) {
        k_gemm_proj<<<dim3(NW/BN, NSLOT/BM), NTHREADS, SMEM_TOTAL>>>(layer, 0);
        k_gemm_proj<<<dim3(18, NCLS/BM), NTHREADS, SMEM_TOTAL>>>(layer, 1);
        k_mix<<<dim3(BB, HH/128), 128>>>(a_cur, a_slot, a_last, a_dom);
        k_gemm_gate<<<dim3(HH/BN, NROW/BM), NTHREADS, SMEM_TOTAL>>>(layer, b_g);
    }
    {
        size_t n = (size_t)BB * 15 * HH;
        k_out<<<(unsigned)((n + 255) / 256), 256>>>(out);
    }
}

// round 5
// speedup vs baseline: 2.6983x; 1.0969x over previous
#include <cuda_runtime.h>
#include <cuda_bf16.h>
#include <math.h>
#include <stdint.h>

#define BB 512
#define SS 30
#define CC 16
#define HH 768
#define NW 3840
#define NSLOT 15360
#define NCLS 8192
#define NROW 23552
#define EPSV 1e-5f

// GEMM tiling
#define BM 128
#define BN 128
#define BK 64
#define NTHREADS 256
#define TILE_BYTES (128*128)            // 16384 (swizzled, no pad)
#define OFF_AH 0
#define OFF_AL TILE_BYTES
#define OFF_BH (2*TILE_BYTES)
#define OFF_BL (3*TILE_BYTES)
#define STAGE  (4*TILE_BYTES)           // 65536
#define NSTAGE 3
#define SMEM_TOTAL (NSTAGE*STAGE)       // 196608

// ---------------- scratch (__device__ globals; no allocations) ----------------
__device__ __align__(128) __nv_bfloat16 g_Xhi[2][(size_t)NROW*HH];
__device__ __align__(128) __nv_bfloat16 g_Xlo[2][(size_t)NROW*HH];
__device__ __align__(128) __nv_bfloat16 g_Uhi[(size_t)NROW*HH];
__device__ __align__(128) __nv_bfloat16 g_Ulo[(size_t)NROW*HH];
__device__ __align__(128) float g_Y[(size_t)NROW*NW];
__device__ __align__(128) __nv_bfloat16 g_Wthi[(size_t)NW*HH];    // [NW][HH]  (B^T for proj)
__device__ __align__(128) __nv_bfloat16 g_Wtlo[(size_t)NW*HH];
__device__ __align__(128) __nv_bfloat16 g_Wgthi[(size_t)HH*2*HH]; // [HH][2*HH] (B^T for gate)
__device__ __align__(128) __nv_bfloat16 g_Wgtlo[(size_t)HH*2*HH];
__device__ float g_bcat[NW];

// ---------------- PTX helpers ----------------
__device__ __forceinline__ uint32_t s2u(const void* p) {
    uint32_t a;
    asm("{ .reg .u64 t; cvta.to.shared.u64 t, %1; cvt.u32.u64 %0, t; }" : "=r"(a) : "l"(p));
    return a;
}
__device__ __forceinline__ void cpa16(uint32_t s, const void* g) {
    asm volatile("cp.async.cg.shared.global [%0], [%1], 16;" :: "r"(s), "l"(g));
}
__device__ __forceinline__ void ldsm_x4(uint32_t addr, uint32_t* r) {
    asm volatile("ldmatrix.sync.aligned.m8n8.x4.shared.b16 {%0,%1,%2,%3}, [%4];"
        : "=r"(r[0]), "=r"(r[1]), "=r"(r[2]), "=r"(r[3]) : "r"(addr));
}
__device__ __forceinline__ void mma16816(float* d, const uint32_t* a, const uint32_t* b) {
    asm volatile("mma.sync.aligned.m16n8k16.row.col.f32.bf16.bf16.f32 "
        "{%0,%1,%2,%3}, {%4,%5,%6,%7}, {%8,%9}, {%0,%1,%2,%3};"
        : "+f"(d[0]), "+f"(d[1]), "+f"(d[2]), "+f"(d[3])
        : "r"(a[0]), "r"(a[1]), "r"(a[2]), "r"(a[3]), "r"(b[0]), "r"(b[1]));
}

__device__ __forceinline__ void split2(float x, __nv_bfloat16& hi, __nv_bfloat16& lo) {
    hi = __float2bfloat16(x);
    lo = __float2bfloat16(x - __bfloat162float(hi));
}

// ---------------- init / pack ----------------
__global__ void k_init(const float* __restrict__ slots, const float* __restrict__ cls) {
    size_t i = (size_t)blockIdx.x * blockDim.x + threadIdx.x;
    if (i >= (size_t)NROW * HH) return;
    const size_t n0 = (size_t)NSLOT * HH;
    float v = (i < n0) ? slots[i] : cls[i - n0];
    split2(v, g_Xhi[0][i], g_Xlo[0][i]);
}
__global__ void k_packW(const float* __restrict__ Ws, const float* __restrict__ bs,
                        const float* __restrict__ Wr, const float* __restrict__ br) {
    size_t i = (size_t)blockIdx.x * blockDim.x + threadIdx.x;
    if (i < (size_t)NW * HH) {
        int j = (int)(i / HH);
        int h = (int)(i % HH);
        int p = j / HH;
        int n = j % HH;
        float w = (p == 0) ? Ws[(size_t)h * HH + n]
                           : Wr[((size_t)(p - 1) * HH + h) * HH + n];
        split2(w, g_Wthi[i], g_Wtlo[i]);
    }
    if (i < NW) {
        int p = (int)(i / HH), n = (int)(i % HH);
        g_bcat[i] = (p == 0) ? bs[n] : br[(size_t)(p - 1) * HH + n];
    }
}
__global__ void k_packG(const float* __restrict__ Wg) {
    size_t i = (size_t)blockIdx.x * blockDim.x + threadIdx.x;
    if (i >= (size_t)HH * 2 * HH) return;
    int j = (int)(i / (2 * HH));
    int k = (int)(i % (2 * HH));
    split2(Wg[(size_t)k * HH + j], g_Wgthi[i], g_Wgtlo[i]);
}

// ---------------- stage loader: 128x64 bf16 tiles, SW128-swizzled ----------------
__device__ __forceinline__ void load_tile(
    uint32_t stg, int tid,
    const __nv_bfloat16* __restrict__ Ah, const __nv_bfloat16* __restrict__ Al,
    size_t a_row0, int a_ld, int ak,
    const __nv_bfloat16* __restrict__ Bh, const __nv_bfloat16* __restrict__ Bl,
    size_t b_row0, int b_ld, int bk) {
#pragma unroll
    for (int t = 0; t < 4; t++) {
        int id = tid + t * NTHREADS;
        int row = id >> 3, c = id & 7;
        uint32_t so = (uint32_t)(row * 128 + ((c * 16) ^ ((row & 7) << 4)));
        size_t ga = (a_row0 + row) * (size_t)a_ld + ak + c * 8;
        cpa16(stg + OFF_AH + so, Ah + ga);
        cpa16(stg + OFF_AL + so, Al + ga);
        size_t gb = (b_row0 + row) * (size_t)b_ld + bk + c * 8;
        cpa16(stg + OFF_BH + so, Bh + gb);
        cpa16(stg + OFF_BL + so, Bl + gb);
    }
}

// ---------------- fragment load for one kk (16-wide K slice) ----------------
// abase = (wm*64 + (lane&15))*128 ; amask = ((lane&15)&7)<<4 ; ak0 = (lane>>4)*16
// bbase = OFF_BH + (wn*32 + (lane>>4)*8 + (lane&7))*128 ; bmask = (lane&7)<<4 ; bk0 = ((lane>>3)&1)*16
__device__ __forceinline__ void load_frags(uint32_t stg,
                                           uint32_t abase, uint32_t ak0, uint32_t amask,
                                           uint32_t bbase, uint32_t bk0, uint32_t bmask,
                                           int kk,
                                           uint32_t ah[4][4], uint32_t al[4][4],
                                           uint32_t bh[4][2], uint32_t bl[4][2]) {
    uint32_t kca = (uint32_t)(kk * 32 + ak0) ^ amask;
    uint32_t kcb = (uint32_t)(kk * 32 + bk0) ^ bmask;
#pragma unroll
    for (int mt = 0; mt < 4; mt++) {
        uint32_t ad = stg + abase + mt * 2048 + kca;
        ldsm_x4(ad, ah[mt]);
        ldsm_x4(ad + TILE_BYTES, al[mt]);
    }
#pragma unroll
    for (int p = 0; p < 2; p++) {
        uint32_t bd = stg + bbase + p * 2048 + kcb;
        uint32_t r[4];
        ldsm_x4(bd, r);
        bh[2*p][0] = r[0]; bh[2*p][1] = r[1];
        bh[2*p+1][0] = r[2]; bh[2*p+1][1] = r[3];
        ldsm_x4(bd + TILE_BYTES, r);
        bl[2*p][0] = r[0]; bl[2*p][1] = r[1];
        bl[2*p+1][0] = r[2]; bl[2*p+1][1] = r[3];
    }
}

// ---------------- per-BK-tile compute: 3-term split-bf16, reg double-buffered ----------------
__device__ __forceinline__ void compute_tile(uint32_t stg,
                                             uint32_t abase, uint32_t ak0, uint32_t amask,
                                             uint32_t bbase, uint32_t bk0, uint32_t bmask,
                                             float acc[4][4][4]) {
    uint32_t ah[2][4][4], al[2][4][4], bh[2][4][2], bl[2][4][2];
    load_frags(stg, abase, ak0, amask, bbase, bk0, bmask, 0, ah[0], al[0], bh[0], bl[0]);
#pragma unroll
    for (int kk = 0; kk < 4; kk++) {
        int cur = kk & 1, nxt = cur ^ 1;
        if (kk < 3)
            load_frags(stg, abase, ak0, amask, bbase, bk0, bmask, kk + 1,
                       ah[nxt], al[nxt], bh[nxt], bl[nxt]);
#pragma unroll
        for (int mt = 0; mt < 4; mt++)
#pragma unroll
            for (int nt = 0; nt < 4; nt++) {
                mma16816(acc[mt][nt], ah[cur][mt], bh[cur][nt]);
                mma16816(acc[mt][nt], ah[cur][mt], bl[cur][nt]);
                mma16816(acc[mt][nt], al[cur][mt], bh[cur][nt]);
            }
    }
}

// ---------------- GEMM 1: Y = X @ Wcat + bcat ----------------
// cls_mode=0: rows [0,NSLOT), all 30 col blocks.
// cls_mode=1: rows [NSLOT,NROW), 18 col blocks remapped to p in {0,1,3}.
__global__ void __launch_bounds__(NTHREADS) k_gemm_proj(int layer, int cls_mode) {
    extern __shared__ __align__(128) char smem[];
    uint32_t sb = s2u(smem);
    const int tid = threadIdx.x, lane = tid & 31, wid = tid >> 5;
    const int wm = wid >> 2, wn = wid & 3;
    int cb = blockIdx.x;
    if (cls_mode && cb >= 12) cb += 6;   // skip p=2 block; cb 12..17 -> 18..23
    const int bn = cb * BN;
    const size_t bm = (cls_mode ? (size_t)NSLOT : 0) + (size_t)blockIdx.y * BM;
    const __nv_bfloat16* __restrict__ Ah = g_Xhi[layer & 1];
    const __nv_bfloat16* __restrict__ Al = g_Xlo[layer & 1];

    float acc[4][4][4];
#pragma unroll
    for (int a = 0; a < 4; a++)
#pragma unroll
        for (int b = 0; b < 4; b++)
#pragma unroll
            for (int c = 0; c < 4; c++) acc[a][b][c] = 0.f;

    const uint32_t abase = (uint32_t)((wm * 64 + (lane & 15)) * 128);
    const uint32_t ak0   = (uint32_t)((lane >> 4) * 16);
    const uint32_t amask = (uint32_t)(((lane & 7)) << 4);
    const uint32_t bbase = OFF_BH + (uint32_t)((wn * 32 + (lane >> 4) * 8 + (lane & 7)) * 128);
    const uint32_t bk0   = (uint32_t)(((lane >> 3) & 1) * 16);
    const uint32_t bmask = (uint32_t)((lane & 7) << 4);

    const int KT = 12;
    load_tile(sb + 0 * STAGE, tid, Ah, Al, bm, HH, 0, g_Wthi, g_Wtlo, bn, HH, 0);
    asm volatile("cp.async.commit_group;");
    load_tile(sb + 1 * STAGE, tid, Ah, Al, bm, HH, BK, g_Wthi, g_Wtlo, bn, HH, BK);
    asm volatile("cp.async.commit_group;");
    for (int kt = 0; kt < KT; kt++) {
        asm volatile("cp.async.wait_group 1;" ::: "memory");
        __syncthreads();
        if (kt + 2 < KT) {
            int nk = kt + 2;
            load_tile(sb + (nk % 3) * STAGE, tid, Ah, Al, bm, HH, nk * BK,
                      g_Wthi, g_Wtlo, bn, HH, nk * BK);
        }
        asm volatile("cp.async.commit_group;");
        compute_tile(sb + (kt % 3) * STAGE, abase, ak0, amask, bbase, bk0, bmask, acc);
    }

    const int gid = lane >> 2, tig = lane & 3;
#pragma unroll
    for (int mt = 0; mt < 4; mt++) {
        size_t r0 = bm + wm * 64 + mt * 16 + gid;
#pragma unroll
        for (int nt = 0; nt < 4; nt++) {
            int col = bn + wn * 32 + nt * 8 + tig * 2;
            float2 bia = *(const float2*)(g_bcat + col);
            float2 v0 = make_float2(acc[mt][nt][0] + bia.x, acc[mt][nt][1] + bia.y);
            float2 v1 = make_float2(acc[mt][nt][2] + bia.x, acc[mt][nt][3] + bia.y);
            *(float2*)(g_Y + r0 * NW + col) = v0;
            *(float2*)(g_Y + (r0 + 8) * NW + col) = v1;
        }
    }
}

// ---------------- GEMM 2: gate = sigmoid([U|X] @ Wg + bg), fused residual ----------------
__global__ void __launch_bounds__(NTHREADS) k_gemm_gate(int layer, const float* __restrict__ bg) {
    extern __shared__ __align__(128) char smem[];
    uint32_t sb = s2u(smem);
    const int tid = threadIdx.x, lane = tid & 31, wid = tid >> 5;
    const int wm = wid >> 2, wn = wid & 3;
    const int bn = blockIdx.x * BN;
    const size_t bm = (size_t)blockIdx.y * BM;
    const __nv_bfloat16* __restrict__ Xh = g_Xhi[layer & 1];
    const __nv_bfloat16* __restrict__ Xl = g_Xlo[layer & 1];
    __nv_bfloat16* __restrict__ Nh = g_Xhi[(layer + 1) & 1];
    __nv_bfloat16* __restrict__ Nl = g_Xlo[(layer + 1) & 1];

    float acc[4][4][4];
#pragma unroll
    for (int a = 0; a < 4; a++)
#pragma unroll
        for (int b = 0; b < 4; b++)
#pragma unroll
            for (int c = 0; c < 4; c++) acc[a][b][c] = 0.f;

    const uint32_t abase = (uint32_t)((wm * 64 + (lane & 15)) * 128);
    const uint32_t ak0   = (uint32_t)((lane >> 4) * 16);
    const uint32_t amask = (uint32_t)(((lane & 7)) << 4);
    const uint32_t bbase = OFF_BH + (uint32_t)((wn * 32 + (lane >> 4) * 8 + (lane & 7)) * 128);
    const uint32_t bk0   = (uint32_t)(((lane >> 3) & 1) * 16);
    const uint32_t bmask = (uint32_t)((lane & 7) << 4);

    const int KT = 24;
    load_tile(sb + 0 * STAGE, tid, g_Uhi, g_Ulo, bm, HH, 0, g_Wgthi, g_Wgtlo, bn, 2 * HH, 0);
    asm volatile("cp.async.commit_group;");
    load_tile(sb + 1 * STAGE, tid, g_Uhi, g_Ulo, bm, HH, BK, g_Wgthi, g_Wgtlo, bn, 2 * HH, BK);
    asm volatile("cp.async.commit_group;");
    for (int kt = 0; kt < KT; kt++) {
        asm volatile("cp.async.wait_group 1;" ::: "memory");
        __syncthreads();
        if (kt + 2 < KT) {
            int nk = kt + 2;
            const __nv_bfloat16* ah = (nk < 12) ? g_Uhi : Xh;
            const __nv_bfloat16* al = (nk < 12) ? g_Ulo : Xl;
            int ak = (nk < 12) ? nk * BK : (nk - 12) * BK;
            load_tile(sb + (nk % 3) * STAGE, tid, ah, al, bm, HH, ak,
                      g_Wgthi, g_Wgtlo, bn, 2 * HH, nk * BK);
        }
        asm volatile("cp.async.commit_group;");
        compute_tile(sb + (kt % 3) * STAGE, abase, ak0, amask, bbase, bk0, bmask, acc);
    }

    const int gid = lane >> 2, tig = lane & 3;
#pragma unroll
    for (int mt = 0; mt < 4; mt++) {
        size_t r0 = bm + wm * 64 + mt * 16 + gid;
#pragma unroll
        for (int nt = 0; nt < 4; nt++) {
            int col = bn + wn * 32 + nt * 8 + tig * 2;
            float2 bia = *(const float2*)(bg + col);
#pragma unroll
            for (int h = 0; h < 2; h++) {
                size_t row = r0 + h * 8;
                size_t base = row * HH + col;
                float rr0 = acc[mt][nt][h * 2 + 0] + bia.x;
                float rr1 = acc[mt][nt][h * 2 + 1] + bia.y;
                float g0 = 1.f / (1.f + __expf(-rr0));
                float g1 = 1.f / (1.f + __expf(-rr1));
                float2 uh = __bfloat1622float2(*(const __nv_bfloat162*)(g_Uhi + base));
                float2 ul = __bfloat1622float2(*(const __nv_bfloat162*)(g_Ulo + base));
                float2 xh = __bfloat1622float2(*(const __nv_bfloat162*)(Xh + base));
                float2 xl = __bfloat1622float2(*(const __nv_bfloat162*)(Xl + base));
                float u0 = uh.x + ul.x, u1 = uh.y + ul.y;
                float x0 = xh.x + xl.x, x1 = xh.y + xl.y;
                float n0 = fmaxf(u0, 0.f) * g0 + x0 * (1.f - g0);
                float n1 = fmaxf(u1, 0.f) * g1 + x1 * (1.f - g1);
                __nv_bfloat16 h0, l0, h1, l1;
                split2(n0, h0, l0);
                split2(n1, h1, l1);
                *(__nv_bfloat162*)(Nh + base) = __nv_bfloat162(h0, h1);
                *(__nv_bfloat162*)(Nl + base) = __nv_bfloat162(l0, l1);
            }
        }
    }
}

// ---------------- mixing: U = Y[:,blk0] + normalized attention messages ----------------
__global__ void __launch_bounds__(128) k_mix(const float* __restrict__ a_cur,
                                             const float* __restrict__ a_slot,
                                             const float* __restrict__ a_last,
                                             const float* __restrict__ a_dom) {
    const int b = blockIdx.x;
    const int k0 = blockIdx.y * 128;
    const int t = threadIdx.x;

    __shared__ float sCur[SS*CC], sLast[SS*CC], sSlot[SS*SS], sDom[SS*SS];
    __shared__ float invColCur[CC], invColLast[CC];
    __shared__ float invRowCur[SS], invRowSlot[SS], invRowLast[SS], invRowDom[SS];
    __shared__ float T0[SS*128];
    __shared__ float T1[SS*128];

    for (int i = t; i < SS*CC; i += 128) {
        sCur[i]  = a_cur [(size_t)b*SS*CC + i];
        sLast[i] = a_last[(size_t)b*SS*CC + i];
    }
    for (int i = t; i < SS*SS; i += 128) {
        sSlot[i] = a_slot[(size_t)b*SS*SS + i];
        sDom[i]  = a_dom [(size_t)b*SS*SS + i];
    }
    __syncthreads();
    if (t < CC) {
        float s1 = 0.f, s2 = 0.f;
        for (int s = 0; s < SS; s++) { s1 += sCur[s*CC+t]; s2 += sLast[s*CC+t]; }
        invColCur[t]  = 1.f / (s1 + EPSV);
        invColLast[t] = 1.f / (s2 + EPSV);
    } else if (t >= 32 && t < 32 + SS) {
        int s = t - 32; float s1 = 0.f, s2 = 0.f;
        for (int c = 0; c < CC; c++) { s1 += sCur[s*CC+c]; s2 += sLast[s*CC+c]; }
        invRowCur[s]  = 1.f / (s1 + EPSV);
        invRowLast[s] = 1.f / (s2 + EPSV);
    } else if (t >= 64 && t < 64 + SS) {
        int s = t - 64; float s1 = 0.f, s2 = 0.f;
        for (int j = 0; j < SS; j++) { s1 += sSlot[s*SS+j]; s2 += sDom[s*SS+j]; }
        invRowSlot[s] = 1.f / (s1 + EPSV);
        invRowDom[s]  = 1.f / (s2 + EPSV);
    }
    __syncthreads();

    // Phase A: cls rows
    for (int s = 0; s < SS; s++) {
        size_t base = (size_t)(b*SS + s) * NW + k0 + t;
        T0[s*128 + t] = g_Y[base + 1*HH];
        T1[s*128 + t] = g_Y[base + 3*HH];
    }
    __syncthreads();
    for (int c = 0; c < CC; c++) {
        float a1 = 0.f, a3 = 0.f;
#pragma unroll
        for (int s = 0; s < SS; s++) {
            a1 += sCur[s*CC+c]  * T0[s*128+t];
            a3 += sLast[s*CC+c] * T1[s*128+t];
        }
        size_t crow = (size_t)NSLOT + (size_t)b*CC + c;
        float v = g_Y[crow * NW + k0 + t] + invColCur[c]*a1 + invColLast[c]*a3;
        size_t idx = crow * HH + k0 + t;
        split2(v, g_Uhi[idx], g_Ulo[idx]);
    }
    __syncthreads();

    // Phase B1
    for (int c = 0; c < CC; c++)
        T0[c*128 + t] = g_Y[((size_t)NSLOT + (size_t)b*CC + c) * NW + 1*HH + k0 + t];
    for (int s = 0; s < SS; s++)
        T1[s*128 + t] = g_Y[(size_t)(b*SS + s) * NW + 2*HH + k0 + t];
    __syncthreads();
    float acc[SS];
#pragma unroll
    for (int s = 0; s < SS; s++) {
        float ac = 0.f, as_ = 0.f;
#pragma unroll
        for (int c = 0; c < CC; c++) ac  += sCur[s*CC+c]  * T0[c*128+t];
#pragma unroll
        for (int j = 0; j < SS; j++) as_ += sSlot[s*SS+j] * T1[j*128+t];
        acc[s] = invRowCur[s]*ac + invRowSlot[s]*as_;
    }
    __syncthreads();

    // Phase B2
    for (int c = 0; c < CC; c++)
        T0[c*128 + t] = g_Y[((size_t)NSLOT + (size_t)b*CC + c) * NW + 3*HH + k0 + t];
    for (int s = 0; s < SS; s++)
        T1[s*128 + t] = g_Y[(size_t)(b*SS + s) * NW + 4*HH + k0 + t];
    __syncthreads();
#pragma unroll
    for (int s = 0; s < SS; s++) {
        float ac = 0.f, as_ = 0.f;
#pragma unroll
        for (int c = 0; c < CC; c++) ac  += sLast[s*CC+c] * T0[c*128+t];
#pragma unroll
        for (int j = 0; j < SS; j++) as_ += sDom[s*SS+j]  * T1[j*128+t];
        acc[s] += invRowLast[s]*ac + invRowDom[s]*as_;
        size_t srow = (size_t)(b*SS + s);
        float v = g_Y[srow * NW + k0 + t] + acc[s];
        size_t idx = srow * HH + k0 + t;
        split2(v, g_Uhi[idx], g_Ulo[idx]);
    }
}

// ---------------- output ----------------
__global__ void k_out(float* __restrict__ out) {
    size_t i = (size_t)blockIdx.x * blockDim.x + threadIdx.x;
    const size_t total = (size_t)BB * 15 * HH;
    if (i >= total) return;
    int k = (int)(i % HH);
    size_t r = i / HH;
    int c = (int)(r % 15) + 1;
    int b = (int)(r / 15);
    size_t idx = ((size_t)NSLOT + (size_t)b*CC + c) * HH + k;
    out[i] = __bfloat162float(g_Xhi[0][idx]) + __bfloat162float(g_Xlo[0][idx]);
}

// ---------------- launch ----------------
extern "C" void kernel_launch(void* const* d_in, const int* in_sizes, int n_in,
                              void* d_out, int out_size) {
    const float* slots  = (const float*)d_in[0];
    const float* cls    = (const float*)d_in[1];
    const float* a_cur  = (const float*)d_in[2];
    const float* a_slot = (const float*)d_in[3];
    const float* a_last = (const float*)d_in[4];
    const float* a_dom  = (const float*)d_in[5];
    const float* W_r    = (const float*)d_in[6];
    const float* b_r    = (const float*)d_in[7];
    const float* W_s    = (const float*)d_in[8];
    const float* b_s    = (const float*)d_in[9];
    const float* W_g    = (const float*)d_in[10];
    const float* b_g    = (const float*)d_in[11];
    float* out = (float*)d_out;

    cudaFuncSetAttribute(k_gemm_proj, cudaFuncAttributeMaxDynamicSharedMemorySize, SMEM_TOTAL);
    cudaFuncSetAttribute(k_gemm_gate, cudaFuncAttributeMaxDynamicSharedMemorySize, SMEM_TOTAL);

    {
        size_t n = (size_t)NROW * HH;
        k_init<<<(unsigned)((n + 1023) / 1024), 1024>>>(slots, cls);
    }
    {
        size_t n = (size_t)NW * HH;
        k_packW<<<(unsigned)((n + 1023) / 1024), 1024>>>(W_s, b_s, W_r, b_r);
    }
    {
        size_t n = (size_t)HH * 2 * HH;
        k_packG<<<(unsigned)((n + 1023) / 1024), 1024>>>(W_g);
    }
    for (int layer = 0; layer < 2; layer++) {
        k_gemm_proj<<<dim3(NW/BN, NSLOT/BM), NTHREADS, SMEM_TOTAL>>>(layer, 0);
        k_gemm_proj<<<dim3(18, NCLS/BM), NTHREADS, SMEM_TOTAL>>>(layer, 1);
        k_mix<<<dim3(BB, HH/128), 128>>>(a_cur, a_slot, a_last, a_dom);
        k_gemm_gate<<<dim3(HH/BN, NROW/BM), NTHREADS, SMEM_TOTAL>>>(layer, b_g);
    }
    {
        size_t n = (size_t)BB * 15 * HH;
        k_out<<<(unsigned)((n + 255) / 256), 256>>>(out);
    }
}